// round 8
// baseline (speedup 1.0000x reference)
#include <cuda_runtime.h>

namespace {

constexpr int RAD   = 7;          // N = 2*ceil(2.5)+1 = 7
constexpr int TBX   = 32;         // threads x
constexpr int TBY   = 4;          // threads y
constexpr int PXY   = 3;          // pixels per thread in y
constexpr int TILEY = TBY * PXY;  // 12 output rows per block
constexpr int SW    = TBX + 2*RAD;    // 46
constexpr int SH    = TILEY + 2*RAD;  // 26
constexpr int IMH   = 1080;
constexpr int IMW   = 1920;
constexpr int CH    = 11;

#define EPSF          1e-4f
#define LOG2E_F       1.4426950408889634f
#define NHALF_LOG2E_F 0.7213475204444817f   /* 0.5*log2(e) */

// INV_DIST[k] = 1/sqrt(k); k=0 sentinel 1e30 so min(invdz*1e30, 1e4) -> 1e4
// (matches reference den = max(dz*0, eps) = eps; zd=0 there so r=0 either way).
__device__ constexpr float INV_DIST[99] = {
    1e30f,       1.0f,        0.70710678f, 0.57735027f, 0.5f,
    0.44721360f, 0.40824829f, 0.37796447f, 0.35355339f, 0.33333333f,
    0.31622777f, 0.30151134f, 0.28867513f, 0.27735010f, 0.26726124f,
    0.25819889f, 0.25f,       0.24253563f, 0.23570226f, 0.22941573f,
    0.22360680f, 0.21821789f, 0.21320072f, 0.20851441f, 0.20412415f,
    0.2f,        0.19611614f, 0.19245009f, 0.18898224f, 0.18569534f,
    0.18257419f, 0.17960530f, 0.17677670f, 0.17407766f, 0.17149859f,
    0.16903085f, 0.16666667f, 0.16439899f, 0.16222142f, 0.16012815f,
    0.15811388f, 0.15617376f, 0.15430335f, 0.15249857f, 0.15075567f,
    0.14907120f, 0.14744196f, 0.14586499f, 0.14433757f, 0.14285714f,
    0.14142136f, 0.14002801f, 0.13867505f, 0.13736056f, 0.13608276f,
    0.13483997f, 0.13363062f, 0.13245324f, 0.13130643f, 0.13018891f,
    0.12909944f, 0.12803688f, 0.12700013f, 0.12598816f, 0.125f,
    0.12403473f, 0.12309149f, 0.12216944f, 0.12126781f, 0.12038585f,
    0.11952286f, 0.11867817f, 0.11785113f, 0.11704115f, 0.11624764f,
    0.11547005f, 0.11470787f, 0.11396058f, 0.11322770f, 0.11250879f,
    0.11180340f, 0.11111111f, 0.11043153f, 0.10976426f, 0.10910895f,
    0.10846523f, 0.10783277f, 0.10721125f, 0.10660036f, 0.10599979f,
    0.10540926f, 0.10482848f, 0.10425721f, 0.10369517f, 0.10314212f,
    0.10259784f, 0.10206207f, 0.10153462f, 0.10101525f
};

__device__ __forceinline__ float ex2f_(float x) {
    float y; asm("ex2.approx.f32 %0, %1;" : "=f"(y) : "f"(x)); return y;
}
__device__ __forceinline__ float lg2f_(float x) {
    float y; asm("lg2.approx.f32 %0, %1;" : "=f"(y) : "f"(x)); return y;
}
__device__ __forceinline__ float rcpf_(float x) {
    float y; asm("rcp.approx.f32 %0, %1;" : "=f"(y) : "f"(x)); return y;
}

struct Pix {
    float Nx, Ny, Nz, Zc, invdz;     // per-pixel constants
    float ar, ag, ab, aw;            // accumulators
};

// One tap for one pixel. invdist/ctap are compile-time constants after unroll.
// w = ex2( 128*lg2(sat(dot)) - log2e*|zt-z|*min(invdz*invdist,1e4) + ctap )
// min(invdz*invdist, 1e4) == 1/max(dzc*dist, 1e-4) for all dzc (dzc<=0 ->
// invdz=+inf -> clamp 1e4 = 1/eps). sat(dot)<=0 -> lg2=-inf -> w=0, identical
// to the reference's eps^128 fp32 underflow.
__device__ __forceinline__ void tap_(
    const float4 nz, const float4 cd, Pix& p,
    float invdist, float ctap)
{
    float dot = __saturatef(fmaf(nz.x, p.Nx, fmaf(nz.y, p.Ny, nz.z * p.Nz)));
    float lt  = lg2f_(dot);

    float factor = fminf(p.invdz * invdist, 1e4f);
    float m      = fabsf(nz.w - p.Zc) * factor;

    float w = ex2f_(fmaf(lt, 128.0f, fmaf(m, -LOG2E_F, ctap)));

    p.ar = fmaf(cd.x, w, p.ar);
    p.ag = fmaf(cd.y, w, p.ag);
    p.ab = fmaf(cd.z, w, p.ab);
    p.aw += w;
}

} // namespace

__global__ void __launch_bounds__(TBX*TBY, 5)
BilateralDenoiser_44427141710593_kernel(const float* __restrict__ in,
                                        float* __restrict__ out)
{
    __shared__ float4 s_nz[SH * SW];   // (nrm.x, nrm.y, nrm.z, z)
    __shared__ float4 s_cd[SH * SW];   // (col.r, col.g, col.b, dz)

    const int bx  = blockIdx.x * TBX;
    const int by  = blockIdx.y * TILEY;
    const int tid = threadIdx.y * TBX + threadIdx.x;

    // Cooperative halo load; OOB -> zeros => dot=0 -> w=0 (matches reference).
    #pragma unroll
    for (int i = tid; i < SH * SW; i += TBX * TBY) {
        const int ly = i / SW;
        const int lx = i - ly * SW;
        const int gy = by + ly - RAD;
        const int gx = bx + lx - RAD;
        float4 nz = make_float4(0.f, 0.f, 0.f, 0.f);
        float4 cd = make_float4(0.f, 0.f, 0.f, 0.f);
        if ((unsigned)gy < (unsigned)IMH && (unsigned)gx < (unsigned)IMW) {
            const float* p = in + ((size_t)gy * IMW + gx) * CH;
            cd.x = p[0]; cd.y = p[1]; cd.z = p[2];      // col
            nz.x = p[3]; nz.y = p[4]; nz.z = p[5];      // nrm
            nz.w = p[9];                                 // z
            cd.w = p[10];                                // dz
        }
        s_nz[i] = nz;
        s_cd[i] = cd;
    }
    __syncthreads();

    // Pixel p (p=0..PXY-1) center is at smem row (threadIdx.y*PXY + RAD + p).
    const int c0 = (threadIdx.y * PXY + RAD) * SW + (threadIdx.x + RAD);
    const float4* __restrict__ snz = s_nz + c0;
    const float4* __restrict__ scd = s_cd + c0;

    Pix px[PXY];
    #pragma unroll
    for (int p = 0; p < PXY; ++p) {
        const float4 n = snz[p * SW];
        px[p].Nx = n.x; px[p].Ny = n.y; px[p].Nz = n.z; px[p].Zc = n.w;
        px[p].invdz = rcpf_(fmaxf(scd[p * SW].w, 0.0f));
        px[p].ar = 0.f; px[p].ag = 0.f; px[p].ab = 0.f; px[p].aw = 0.f;
    }

    // dy spans the union of all PXY pixels' [-7,7] windows; one smem load per
    // (dy,dx) feeds every pixel whose window covers it (compile-time masks).
    #pragma unroll
    for (int dy = -RAD; dy <= RAD + PXY - 1; ++dy) {
        #pragma unroll
        for (int dx = -RAD; dx <= RAD; ++dx) {
            const float4 nz = snz[dy*SW + dx];
            const float4 cd = scd[dy*SW + dx];
            #pragma unroll
            for (int p = 0; p < PXY; ++p) {
                if (dy - p >= -RAD && dy - p <= RAD) {   // compile-time
                    const int dsi = (dy-p)*(dy-p) + dx*dx;
                    tap_(nz, cd, px[p], INV_DIST[dsi], -NHALF_LOG2E_F * dsi);
                }
            }
        }
    }

    const int gx  = bx + threadIdx.x;
    const int gy0 = by + threadIdx.y * PXY;
    #pragma unroll
    for (int p = 0; p < PXY; ++p) {
        const float inv = 1.0f / fmaxf(px[p].aw, EPSF);
        float* o = out + ((size_t)(gy0 + p) * IMW + gx) * 3;
        o[0] = px[p].ar * inv;
        o[1] = px[p].ag * inv;
        o[2] = px[p].ab * inv;
    }
}

extern "C" void kernel_launch(void* const* d_in, const int* in_sizes, int n_in,
                              void* d_out, int out_size)
{
    const float* in = (const float*)d_in[0];
    float* out = (float*)d_out;
    dim3 block(TBX, TBY);
    dim3 grid(IMW / TBX, IMH / TILEY);   // 60 x 90, exact tiling
    BilateralDenoiser_44427141710593_kernel<<<grid, block>>>(in, out);
}

// round 9
// speedup vs baseline: 1.0248x; 1.0248x over previous
#include <cuda_runtime.h>

namespace {

constexpr int RAD   = 7;          // N = 2*ceil(2.5)+1 = 7
constexpr int TBX   = 32;         // threads x
constexpr int TBY   = 6;          // threads y
constexpr int PXY   = 2;          // pixels per thread in y
constexpr int TILEY = TBY * PXY;  // 12 output rows per block (1080/12 = 90)
constexpr int SW    = TBX + 2*RAD;    // 46
constexpr int SH    = TILEY + 2*RAD;  // 26
constexpr int IMH   = 1080;
constexpr int IMW   = 1920;
constexpr int CH    = 11;

#define EPSF          1e-4f
#define LOG2E_F       1.4426950408889634f
#define NHALF_LOG2E_F 0.7213475204444817f   /* 0.5*log2(e) */

// INV_DIST[k] = 1/sqrt(k); k=0 sentinel 1e30 so min(invdz*1e30, 1e4) -> 1e4
// (matches reference den = max(dz*0, eps) = eps; zd=0 there so r=0 either way).
__device__ constexpr float INV_DIST[99] = {
    1e30f,       1.0f,        0.70710678f, 0.57735027f, 0.5f,
    0.44721360f, 0.40824829f, 0.37796447f, 0.35355339f, 0.33333333f,
    0.31622777f, 0.30151134f, 0.28867513f, 0.27735010f, 0.26726124f,
    0.25819889f, 0.25f,       0.24253563f, 0.23570226f, 0.22941573f,
    0.22360680f, 0.21821789f, 0.21320072f, 0.20851441f, 0.20412415f,
    0.2f,        0.19611614f, 0.19245009f, 0.18898224f, 0.18569534f,
    0.18257419f, 0.17960530f, 0.17677670f, 0.17407766f, 0.17149859f,
    0.16903085f, 0.16666667f, 0.16439899f, 0.16222142f, 0.16012815f,
    0.15811388f, 0.15617376f, 0.15430335f, 0.15249857f, 0.15075567f,
    0.14907120f, 0.14744196f, 0.14586499f, 0.14433757f, 0.14285714f,
    0.14142136f, 0.14002801f, 0.13867505f, 0.13736056f, 0.13608276f,
    0.13483997f, 0.13363062f, 0.13245324f, 0.13130643f, 0.13018891f,
    0.12909944f, 0.12803688f, 0.12700013f, 0.12598816f, 0.125f,
    0.12403473f, 0.12309149f, 0.12216944f, 0.12126781f, 0.12038585f,
    0.11952286f, 0.11867817f, 0.11785113f, 0.11704115f, 0.11624764f,
    0.11547005f, 0.11470787f, 0.11396058f, 0.11322770f, 0.11250879f,
    0.11180340f, 0.11111111f, 0.11043153f, 0.10976426f, 0.10910895f,
    0.10846523f, 0.10783277f, 0.10721125f, 0.10660036f, 0.10599979f,
    0.10540926f, 0.10482848f, 0.10425721f, 0.10369517f, 0.10314212f,
    0.10259784f, 0.10206207f, 0.10153462f, 0.10101525f
};

__device__ __forceinline__ float ex2f_(float x) {
    float y; asm("ex2.approx.f32 %0, %1;" : "=f"(y) : "f"(x)); return y;
}
__device__ __forceinline__ float lg2f_(float x) {
    float y; asm("lg2.approx.f32 %0, %1;" : "=f"(y) : "f"(x)); return y;
}
__device__ __forceinline__ float rcpf_(float x) {
    float y; asm("rcp.approx.f32 %0, %1;" : "=f"(y) : "f"(x)); return y;
}

struct Pix {
    float Nx, Ny, Nz, Zc, invdz;     // per-pixel constants
    float ar, ag, ab, aw;            // accumulators
};

// One tap for one pixel. invdist/ctap are compile-time constants after unroll.
// w = ex2( 128*lg2(sat(dot)) - log2e*|zt-z|*min(invdz*invdist,1e4) + ctap )
// min(invdz*invdist, 1e4) == 1/max(dzc*dist, 1e-4) for all dzc (dzc<=0 ->
// invdz=+inf -> clamp 1e4 = 1/eps). sat(dot)<=0 -> lg2=-inf -> w=0, identical
// to the reference's eps^128 fp32 underflow.
__device__ __forceinline__ void tap_(
    const float4 nz, const float4 cd, Pix& p,
    float invdist, float ctap)
{
    float dot = __saturatef(fmaf(nz.x, p.Nx, fmaf(nz.y, p.Ny, nz.z * p.Nz)));
    float lt  = lg2f_(dot);

    float factor = fminf(p.invdz * invdist, 1e4f);
    float m      = fabsf(nz.w - p.Zc) * factor;

    float w = ex2f_(fmaf(lt, 128.0f, fmaf(m, -LOG2E_F, ctap)));

    p.ar = fmaf(cd.x, w, p.ar);
    p.ag = fmaf(cd.y, w, p.ag);
    p.ab = fmaf(cd.z, w, p.ab);
    p.aw += w;
}

} // namespace

__global__ void __launch_bounds__(TBX*TBY, 5)
BilateralDenoiser_44427141710593_kernel(const float* __restrict__ in,
                                        float* __restrict__ out)
{
    __shared__ float4 s_nz[SH * SW];   // (nrm.x, nrm.y, nrm.z, z)
    __shared__ float4 s_cd[SH * SW];   // (col.r, col.g, col.b, dz)

    const int bx  = blockIdx.x * TBX;
    const int by  = blockIdx.y * TILEY;
    const int tid = threadIdx.y * TBX + threadIdx.x;

    // Cooperative halo load; OOB -> zeros => dot=0 -> w=0 (matches reference).
    #pragma unroll
    for (int i = tid; i < SH * SW; i += TBX * TBY) {
        const int ly = i / SW;
        const int lx = i - ly * SW;
        const int gy = by + ly - RAD;
        const int gx = bx + lx - RAD;
        float4 nz = make_float4(0.f, 0.f, 0.f, 0.f);
        float4 cd = make_float4(0.f, 0.f, 0.f, 0.f);
        if ((unsigned)gy < (unsigned)IMH && (unsigned)gx < (unsigned)IMW) {
            const float* p = in + ((size_t)gy * IMW + gx) * CH;
            cd.x = p[0]; cd.y = p[1]; cd.z = p[2];      // col
            nz.x = p[3]; nz.y = p[4]; nz.z = p[5];      // nrm
            nz.w = p[9];                                 // z
            cd.w = p[10];                                // dz
        }
        s_nz[i] = nz;
        s_cd[i] = cd;
    }
    __syncthreads();

    // Pixel p (p=0..PXY-1) center is at smem row (threadIdx.y*PXY + RAD + p).
    const int c0 = (threadIdx.y * PXY + RAD) * SW + (threadIdx.x + RAD);
    const float4* __restrict__ snz = s_nz + c0;
    const float4* __restrict__ scd = s_cd + c0;

    Pix px[PXY];
    #pragma unroll
    for (int p = 0; p < PXY; ++p) {
        const float4 n = snz[p * SW];
        px[p].Nx = n.x; px[p].Ny = n.y; px[p].Nz = n.z; px[p].Zc = n.w;
        px[p].invdz = rcpf_(fmaxf(scd[p * SW].w, 0.0f));
        px[p].ar = 0.f; px[p].ag = 0.f; px[p].ab = 0.f; px[p].aw = 0.f;
    }

    // dy spans the union of all PXY pixels' [-7,7] windows; one smem load per
    // (dy,dx) feeds every pixel whose window covers it (compile-time masks).
    #pragma unroll
    for (int dy = -RAD; dy <= RAD + PXY - 1; ++dy) {
        #pragma unroll
        for (int dx = -RAD; dx <= RAD; ++dx) {
            const float4 nz = snz[dy*SW + dx];
            const float4 cd = scd[dy*SW + dx];
            #pragma unroll
            for (int p = 0; p < PXY; ++p) {
                if (dy - p >= -RAD && dy - p <= RAD) {   // compile-time
                    const int dsi = (dy-p)*(dy-p) + dx*dx;
                    tap_(nz, cd, px[p], INV_DIST[dsi], -NHALF_LOG2E_F * dsi);
                }
            }
        }
    }

    const int gx  = bx + threadIdx.x;
    const int gy0 = by + threadIdx.y * PXY;
    #pragma unroll
    for (int p = 0; p < PXY; ++p) {
        const float inv = 1.0f / fmaxf(px[p].aw, EPSF);
        float* o = out + ((size_t)(gy0 + p) * IMW + gx) * 3;
        o[0] = px[p].ar * inv;
        o[1] = px[p].ag * inv;
        o[2] = px[p].ab * inv;
    }
}

extern "C" void kernel_launch(void* const* d_in, const int* in_sizes, int n_in,
                              void* d_out, int out_size)
{
    const float* in = (const float*)d_in[0];
    float* out = (float*)d_out;
    dim3 block(TBX, TBY);
    dim3 grid(IMW / TBX, IMH / TILEY);   // 60 x 90, exact tiling
    BilateralDenoiser_44427141710593_kernel<<<grid, block>>>(in, out);
}

// round 10
// speedup vs baseline: 1.1355x; 1.1081x over previous
#include <cuda_runtime.h>

namespace {

constexpr int RAD   = 7;          // N = 2*ceil(2.5)+1 = 7
constexpr int TBX   = 32;         // threads x
constexpr int TBY   = 6;          // threads y
constexpr int PXY   = 2;          // pixels per thread in y
constexpr int TILEY = TBY * PXY;  // 12 output rows per block (1080/12 = 90)
constexpr int SW    = TBX + 2*RAD;    // 46
constexpr int SH    = TILEY + 2*RAD;  // 26
constexpr int IMH   = 1080;
constexpr int IMW   = 1920;
constexpr int CH    = 11;

#define EPSF      1e-4f
#define LOG2E_F   1.4426950408889634f
// cap = 1e4 * log2e  (factor' = log2e * min(invdz*invdist, 1e4))
#define FCAP      14426.950408889634f

// INVD_L2E[k] = log2(e)/sqrt(k); k=0 sentinel 1e30 so min(invdz*1e30, FCAP)
// -> FCAP (matches reference den = max(dz*0, eps) = eps; zd=0 there anyway).
__device__ constexpr float INVD_L2E[99] = {
    1e30f,       1.44269504f, 1.02014424f, 0.83293944f, 0.72134752f,
    0.64519935f, 0.58898486f, 0.54529656f, 0.51007212f, 0.48089835f,
    0.45621984f, 0.43498237f, 0.41646972f, 0.40012747f, 0.38556183f,
    0.37247373f, 0.36067376f, 0.34990480f, 0.34009409f, 0.33102480f,
    0.32259967f, 0.31482513f, 0.30758643f, 0.30082509f, 0.29449243f,
    0.28853901f, 0.28293539f, 0.27764648f, 0.27264828f, 0.26790684f,
    0.26340594f, 0.25912240f, 0.25503606f, 0.25114328f, 0.24742265f,
    0.24386200f, 0.24044918f, 0.23717857f, 0.23403768f, 0.23101807f,
    0.22810992f, 0.22531137f, 0.22261272f, 0.22000923f, 0.21749119f,
    0.21506125f, 0.21271045f, 0.21043517f, 0.20823486f, 0.20609929f,
    0.20403378f, 0.20202950f, 0.20008659f, 0.19819969f, 0.19636738f,
    0.19458680f, 0.19284900f, 0.19115746f, 0.18950668f, 0.18789521f,
    0.18633688f, 0.18480333f, 0.18331146f, 0.18184540f, 0.18041844f,
    0.17902041f, 0.17766033f, 0.17632993f, 0.17501816f, 0.17374384f,
    0.17248900f, 0.17126993f, 0.17004704f, 0.16888040f, 0.16773528f,
    0.16659174f, 0.16549221f, 0.16440389f, 0.16334410f, 0.16231653f,
    0.16129984f, 0.16029945f, 0.15932285f, 0.15835942f, 0.15741374f,
    0.15648424f, 0.15557203f, 0.15467385f, 0.15379850f, 0.15293093f,
    0.15207893f, 0.15123993f, 0.15041596f, 0.14960526f, 0.14880778f,
    0.14801817f, 0.14724766f, 0.14648368f, 0.14574043f
};

__device__ __forceinline__ float ex2f_(float x) {
    float y; asm("ex2.approx.f32 %0, %1;" : "=f"(y) : "f"(x)); return y;
}
__device__ __forceinline__ float lg2f_(float x) {
    float y; asm("lg2.approx.f32 %0, %1;" : "=f"(y) : "f"(x)); return y;
}
__device__ __forceinline__ float rcpf_(float x) {
    float y; asm("rcp.approx.f32 %0, %1;" : "=f"(y) : "f"(x)); return y;
}

// ---- packed f32x2 helpers (sm_103a) ----
__device__ __forceinline__ unsigned long long pack2_(float lo, float hi) {
    unsigned long long d;
    asm("mov.b64 %0, {%1, %2};" : "=l"(d) : "f"(lo), "f"(hi));
    return d;
}
__device__ __forceinline__ void unpack2_(float& lo, float& hi, unsigned long long v) {
    asm("mov.b64 {%0, %1}, %2;" : "=f"(lo), "=f"(hi) : "l"(v));
}
__device__ __forceinline__ void fma2_(unsigned long long& d,
                                      unsigned long long a,
                                      unsigned long long b) {
    asm("fma.rn.f32x2 %0, %1, %2, %0;" : "+l"(d) : "l"(a), "l"(b));
}
__device__ __forceinline__ void add2_(unsigned long long& d, unsigned long long a) {
    asm("add.rn.f32x2 %0, %0, %1;" : "+l"(d) : "l"(a));
}

struct Pix {
    float Nx, Ny, Nz, Zc, invdz;     // per-pixel constants
};

} // namespace

__global__ void __launch_bounds__(TBX*TBY, 5)
BilateralDenoiser_44427141710593_kernel(const float* __restrict__ in,
                                        float* __restrict__ out)
{
    __shared__ float4 s_nz[SH * SW];   // (nrm.x, nrm.y, nrm.z, z)
    __shared__ float4 s_cd[SH * SW];   // (col.r, col.g, col.b, dz)

    const int bx  = blockIdx.x * TBX;
    const int by  = blockIdx.y * TILEY;
    const int tid = threadIdx.y * TBX + threadIdx.x;

    // Cooperative halo load; OOB -> zeros => dot=0 -> w=0 (matches reference's
    // eps^128 fp32 underflow).
    #pragma unroll
    for (int i = tid; i < SH * SW; i += TBX * TBY) {
        const int ly = i / SW;
        const int lx = i - ly * SW;
        const int gy = by + ly - RAD;
        const int gx = bx + lx - RAD;
        float4 nz = make_float4(0.f, 0.f, 0.f, 0.f);
        float4 cd = make_float4(0.f, 0.f, 0.f, 0.f);
        if ((unsigned)gy < (unsigned)IMH && (unsigned)gx < (unsigned)IMW) {
            const float* p = in + ((size_t)gy * IMW + gx) * CH;
            cd.x = p[0]; cd.y = p[1]; cd.z = p[2];      // col
            nz.x = p[3]; nz.y = p[4]; nz.z = p[5];      // nrm
            nz.w = p[9];                                 // z
            cd.w = p[10];                                // dz
        }
        s_nz[i] = nz;
        s_cd[i] = cd;
    }
    __syncthreads();

    const int c0 = (threadIdx.y * PXY + RAD) * SW + (threadIdx.x + RAD);
    const float4* __restrict__ snz = s_nz + c0;
    const float4* __restrict__ scd = s_cd + c0;

    Pix px[PXY];
    #pragma unroll
    for (int p = 0; p < PXY; ++p) {
        const float4 n = snz[p * SW];
        px[p].Nx = n.x; px[p].Ny = n.y; px[p].Nz = n.z; px[p].Zc = n.w;
        px[p].invdz = rcpf_(fmaxf(scd[p * SW].w, 0.0f));
    }

    // Packed accumulators: lane0 = pixel0, lane1 = pixel1.
    unsigned long long ar2 = 0ull, ag2 = 0ull, ab2 = 0ull, aw2 = 0ull;

    // One smem load per (dy,dx) feeds pixel0's tap (dy) and pixel1's (dy-1).
    // Edge rows (dy=-RAD for p1, dy=RAD+1 for p0) get a zero weight via
    // ctap = -inf-ish, preserving the shared packed accumulation.
    #pragma unroll
    for (int dy = -RAD; dy <= RAD + 1; ++dy) {
        #pragma unroll
        for (int dx = -RAD; dx <= RAD; ++dx) {
            const float4 nz = snz[dy*SW + dx];
            const float4 cd = scd[dy*SW + dx];

            // -------- pixel 0 (offset dy) --------
            float w0 = 0.0f;
            if (dy <= RAD) {                            // compile-time
                const int dsi = dy*dy + dx*dx;
                const float ctap = -0.72134752044448f * (float)dsi;
                float dot = __saturatef(fmaf(nz.x, px[0].Nx,
                              fmaf(nz.y, px[0].Ny, nz.z * px[0].Nz)));
                float lt  = lg2f_(dot);
                float fp  = fminf(px[0].invdz * INVD_L2E[dsi], FCAP);
                float zd  = nz.w - px[0].Zc;
                w0 = ex2f_(fmaf(lt, 128.0f, fmaf(fabsf(zd), -fp, ctap)));
            }
            // -------- pixel 1 (offset dy-1) --------
            float w1 = 0.0f;
            if (dy >= -RAD + 1) {                       // compile-time
                const int dsi = (dy-1)*(dy-1) + dx*dx;
                const float ctap = -0.72134752044448f * (float)dsi;
                float dot = __saturatef(fmaf(nz.x, px[1].Nx,
                              fmaf(nz.y, px[1].Ny, nz.z * px[1].Nz)));
                float lt  = lg2f_(dot);
                float fp  = fminf(px[1].invdz * INVD_L2E[dsi], FCAP);
                float zd  = nz.w - px[1].Zc;
                w1 = ex2f_(fmaf(lt, 128.0f, fmaf(fabsf(zd), -fp, ctap)));
            }

            // -------- packed accumulation (both pixels) --------
            const unsigned long long w01 = pack2_(w0, w1);
            fma2_(ar2, pack2_(cd.x, cd.x), w01);
            fma2_(ag2, pack2_(cd.y, cd.y), w01);
            fma2_(ab2, pack2_(cd.z, cd.z), w01);
            add2_(aw2, w01);
        }
    }

    float ar0, ar1, ag0, ag1, ab0, ab1, aw0, aw1;
    unpack2_(ar0, ar1, ar2);
    unpack2_(ag0, ag1, ag2);
    unpack2_(ab0, ab1, ab2);
    unpack2_(aw0, aw1, aw2);

    const int gx  = bx + threadIdx.x;
    const int gy0 = by + threadIdx.y * PXY;
    {
        const float inv = 1.0f / fmaxf(aw0, EPSF);
        float* o = out + ((size_t)gy0 * IMW + gx) * 3;
        o[0] = ar0 * inv; o[1] = ag0 * inv; o[2] = ab0 * inv;
    }
    {
        const float inv = 1.0f / fmaxf(aw1, EPSF);
        float* o = out + ((size_t)(gy0 + 1) * IMW + gx) * 3;
        o[0] = ar1 * inv; o[1] = ag1 * inv; o[2] = ab1 * inv;
    }
}

extern "C" void kernel_launch(void* const* d_in, const int* in_sizes, int n_in,
                              void* d_out, int out_size)
{
    const float* in = (const float*)d_in[0];
    float* out = (float*)d_out;
    dim3 block(TBX, TBY);
    dim3 grid(IMW / TBX, IMH / TILEY);   // 60 x 90, exact tiling
    BilateralDenoiser_44427141710593_kernel<<<grid, block>>>(in, out);
}